// round 8
// baseline (speedup 1.0000x reference)
#include <cuda_runtime.h>
#include <cuda_bf16.h>
#include <math.h>

// Problem constants
#define BSZ   8
#define MROW  64
#define NCOL  4096
#define KSEL  32
#define NPAIR (BSZ * MROW)        // 512 (b,m) pairs
#define NROWS (NPAIR * KSEL)      // 16384 output rows / blocks
#define TPB   256                 // 8 warps
#define VPT   16                  // logits per thread (4096/256)
#define NBKT  4096                // histogram buckets (top 12 bits of fmap)
#define CAP   2048                // candidate cap (expected ~50-100)

// Noise bounds: gn = -0.001*log(-log(u+1e-20)+1e-20) in [-0.003830, +0.046052],
// span < 0.04989 -> margin 0.06 is strictly safe.
#define MARGIN 0.06f

// Static scratch (no allocation allowed)
__device__ int g_idx[NROWS];
__device__ int g_flag[NPAIR];

// Order-preserving float->uint map: a > b  <=>  fmap(a) > fmap(b). Bijective.
__device__ __forceinline__ unsigned fmap(float f) {
    unsigned b = __float_as_uint(f);
    return b ^ ((unsigned)(((int)b) >> 31) | 0x80000000u);
}
__device__ __forceinline__ float unfmap(unsigned m) {
    unsigned b = (m & 0x80000000u) ? (m ^ 0x80000000u) : ~m;
    return __uint_as_float(b);
}

// ---------------------------------------------------------------------------
// Reset flags each replay (graph-replay safety).
// ---------------------------------------------------------------------------
__global__ void reset_kernel()
{
    g_flag[threadIdx.x] = 0;
}

// ---------------------------------------------------------------------------
// Fused kernel: 16384 blocks. Block b fills row (b&511)*32 + (b>>9).
// Blocks b<512 first run the exact top-32 select for bm=b (round-7 algorithm),
// publish g_idx + release flag; other blocks acquire the flag for their bm.
// ---------------------------------------------------------------------------
__global__ __launch_bounds__(TPB)
void fused_kernel(const float* __restrict__ logits,
                  const float* __restrict__ u,
                  float* __restrict__ out)
{
    const int b    = blockIdx.x;            // 0..16383
    const int bmf  = b & (NPAIR - 1);       // bm whose row this block fills
    const int sub  = b >> 9;                // which of the 32 rows
    const int t    = threadIdx.x;

    // hist is dead before keys are written -> overlay (16 KB total)
    __shared__ union {
        int                s_hist[NBKT];    // 16 KB
        unsigned long long s_keys[CAP];     // 16 KB
    } ov;
    __shared__ int s_top[KSEL];
    __shared__ int s_cnt;
    __shared__ int s_bkt;

    if (b < NPAIR) {
        // =================== SELECT for bm = b ===================
        const int bm   = b;
        const int m    = bm & (MROW - 1);
        const int lane = t & 31;
        const int warp = t >> 5;

        // ---- Load logits row into registers (L2-hot: 64 distinct rows) ----
        const int base = t * VPT;
        const float4* __restrict__ l4 = (const float4*)(logits + (size_t)m * NCOL);
        float f[VPT];
#pragma unroll
        for (int q = 0; q < 4; q++) {
            float4 ll = l4[(base >> 2) + q];
            f[q*4+0] = ll.x; f[q*4+1] = ll.y; f[q*4+2] = ll.z; f[q*4+3] = ll.w;
        }

        // ---- Zero histogram ----
#pragma unroll
        for (int i = 0; i < NBKT / (TPB * 4); i++)
            ((int4*)ov.s_hist)[t + i * TPB] = make_int4(0, 0, 0, 0);
        if (t == 0) s_cnt = 0;

        // ---- Per-thread top-4 prefilter (mapped-uint domain) ----
        unsigned um[VPT];
#pragma unroll
        for (int j = 0; j < VPT; j++) um[j] = fmap(f[j]);

        int      tj[4];
        unsigned tmu[4];
#pragma unroll
        for (int p = 0; p < 4; p++) {
            unsigned bv = um[0];
            int bj = 0;
#pragma unroll
            for (int j = 1; j < VPT; j++) if (um[j] > bv) { bv = um[j]; bj = j; }
            tj[p] = bj; tmu[p] = bv;
#pragma unroll
            for (int j = 0; j < VPT; j++) if (j == bj) um[j] = 0u;
        }

        // ---- Prefetch u for the 4 local-top candidates ----
        const float* __restrict__ urow = u + (size_t)bm * NCOL;
        float uu[4];
#pragma unroll
        for (int p = 0; p < 4; p++) uu[p] = urow[base + tj[p]];

        __syncthreads();   // hist zeroed

        // ---- Filtered histogram: 4 atomics/thread (under-count conservative)
#pragma unroll
        for (int p = 0; p < 4; p++)
            atomicAdd(&ov.s_hist[tmu[p] >> 20], 1);
        __syncthreads();

        // ---- Warp 0: chunk scan for bucket where filtered-cum reaches 32 ----
        if (warp == 0) {
            const unsigned FULL = 0xffffffffu;
            int cum = 0;
            for (int bb = NBKT - 64; bb >= 0; bb -= 64) {
                const int2 c = ((const int2*)(ov.s_hist + bb))[lane];
                const int pair  = c.x + c.y;
                const int total = __reduce_add_sync(FULL, pair);
                if (cum + total >= KSEL) {
                    int suf = pair;   // inclusive suffix sum over lanes
#pragma unroll
                    for (int off = 1; off < 32; off <<= 1) {
                        const int o = __shfl_down_sync(FULL, suf, off);
                        if (lane + off < 32) suf += o;
                    }
                    const int cx = cum + suf;
                    const unsigned bal = __ballot_sync(FULL, cx >= KSEL);
                    const int hi = 31 - __clz(bal);
                    if (lane == hi) {
                        const int cy = cx - c.x;
                        s_bkt = bb + lane * 2 + ((cy >= KSEL) ? 1 : 0);
                    }
                    break;
                }
                cum += total;
            }
        }

        // ---- Compute keys for prefetched candidates (overlaps scan) ----
        unsigned long long pkey[4];
#pragma unroll
        for (int p = 0; p < 4; p++) {
            const float gn  = -0.001f * __logf(-__logf(uu[p] + 1e-20f) + 1e-20f);
            const float val = unfmap(tmu[p]) + gn;
            pkey[p] = ((unsigned long long)fmap(val) << 32)
                    | (unsigned)(~(base + tj[p]));
        }
        __syncthreads();   // s_bkt ready; hist dead from here (union -> keys)

        // ---- Candidate gather: logit >= bucket_edge - MARGIN ----
        const float thrf = unfmap((unsigned)s_bkt << 20) - MARGIN;
        int nq = 0;
#pragma unroll
        for (int j = 0; j < VPT; j++) nq += (f[j] >= thrf) ? 1 : 0;

        if (nq <= 4) {
#pragma unroll
            for (int p = 0; p < 4; p++) {
                if (unfmap(tmu[p]) >= thrf) {
                    const int pos = atomicAdd(&s_cnt, 1);
                    if (pos < CAP) ov.s_keys[pos] = pkey[p];
                }
            }
        } else {
            // rare: thread holds >4 qualifying values — exact slow path
#pragma unroll
            for (int j = 0; j < VPT; j++) {
                if (f[j] >= thrf) {
                    const int pos = atomicAdd(&s_cnt, 1);
                    if (pos < CAP) {
                        const int idx = base + j;
                        const float u2 = urow[idx];
                        const float gn = -0.001f * __logf(-__logf(u2 + 1e-20f) + 1e-20f);
                        const float val = f[j] + gn;
                        ov.s_keys[pos] = ((unsigned long long)fmap(val) << 32)
                                       | (unsigned)(~idx);
                    }
                }
            }
        }
        __syncthreads();

        // ---- Parallel rank-count top-32 (all 256 threads) ----
        const int cnt = min(s_cnt, CAP);     // >= KSEL by construction
        for (int i = t; i < cnt; i += TPB) {
            const unsigned long long k = ov.s_keys[i];
            int r = 0;
            for (int j = 0; j < cnt; j++)
                r += (ov.s_keys[j] > k) ? 1 : 0;   // unique keys -> unique ranks
            if (r < KSEL) s_top[r] = (int)(~(unsigned)k);
        }
        __syncthreads();

        // ---- Index-rank sort -> ascending; publish + release flag ----
        if (t < KSEL) {
            const int myidx = s_top[t];
            int rank = 0;
#pragma unroll
            for (int j = 0; j < KSEL; j++) rank += (s_top[j] < myidx) ? 1 : 0;
            g_idx[bm * KSEL + rank] = myidx;
            __threadfence();                 // each writer fences its store
        }
        __syncthreads();
        if (t == 0) atomicExch(&g_flag[bm], 1);
    } else {
        // =================== WAIT for bm = bmf ===================
        if (t == 0) {
            while (atomicAdd(&g_flag[bmf], 0) == 0) __nanosleep(64);
            __threadfence();                 // acquire ordering for g_idx reads
        }
        __syncthreads();
    }

    // =================== FILL row r ===================
    const int r = bmf * KSEL + sub;
    const int target = g_idx[r];
    float4* __restrict__ o = reinterpret_cast<float4*>(out + (size_t)r * NCOL);

#pragma unroll
    for (int i = 0; i < 4; i++) {
        const int slot = t + i * TPB;        // float4 slot 0..1023
        const int n0 = slot * 4;
        float4 val;
        val.x = (target == n0    ) ? 1.0f : 0.0f;
        val.y = (target == n0 + 1) ? 1.0f : 0.0f;
        val.z = (target == n0 + 2) ? 1.0f : 0.0f;
        val.w = (target == n0 + 3) ? 1.0f : 0.0f;
        o[slot] = val;
    }
}

extern "C" void kernel_launch(void* const* d_in, const int* in_sizes, int n_in,
                              void* d_out, int out_size)
{
    const float* logits = (const float*)d_in[0];   // (64, 4096) fp32
    const float* u      = (const float*)d_in[1];   // (8, 64, 4096) fp32
    float*       out    = (float*)d_out;           // (8, 64, 32, 4096) fp32

    reset_kernel<<<1, NPAIR>>>();
    fused_kernel<<<NROWS, TPB>>>(logits, u, out);
}

// round 9
// speedup vs baseline: 1.1461x; 1.1461x over previous
#include <cuda_runtime.h>
#include <cuda_bf16.h>
#include <math.h>

// Problem constants
#define BSZ   8
#define MROW  64
#define NCOL  4096
#define KSEL  32
#define NPAIR (BSZ * MROW)        // 512 (b,m) pairs
#define NROWS (NPAIR * KSEL)      // 16384 output rows / blocks
#define TPB   256                 // 8 warps
#define VPT   16                  // logits per thread (4096/256)
#define NBKT  4096                // histogram buckets (top 12 bits of fmap)
#define CAP   2048                // candidate cap (expected ~50-100)

// Noise bounds: gn = -0.001*log(-log(u+1e-20)+1e-20) in [-0.003830, +0.046052],
// span < 0.04989 -> margin 0.06 is strictly safe.
#define MARGIN 0.06f

// Static scratch (no allocation allowed)
__device__ int g_idx[NROWS];
__device__ int g_flag[NPAIR];

// Order-preserving float->uint map: a > b  <=>  fmap(a) > fmap(b). Bijective.
__device__ __forceinline__ unsigned fmap(float f) {
    unsigned b = __float_as_uint(f);
    return b ^ ((unsigned)(((int)b) >> 31) | 0x80000000u);
}
__device__ __forceinline__ float unfmap(unsigned m) {
    unsigned b = (m & 0x80000000u) ? (m ^ 0x80000000u) : ~m;
    return __uint_as_float(b);
}

// ---------------------------------------------------------------------------
// Reset flags each replay (graph-replay safety).
// ---------------------------------------------------------------------------
__global__ void reset_kernel()
{
    g_flag[threadIdx.x] = 0;
}

// ---------------------------------------------------------------------------
// Fused kernel: 16384 blocks; block b owns row (b&511)*32 + (b>>9).
// b<512: run exact top-32 select for bm=b, publish g_idx + release flag.
// ALL blocks: write their row of zeros IMMEDIATELY (no dependency), then
// acquire the flag (already set by then) and store the single 1.0.
// ---------------------------------------------------------------------------
__global__ __launch_bounds__(TPB)
void fused_kernel(const float* __restrict__ logits,
                  const float* __restrict__ u,
                  float* __restrict__ out)
{
    const int b    = blockIdx.x;            // 0..16383
    const int bmf  = b & (NPAIR - 1);       // bm whose row this block fills
    const int sub  = b >> 9;                // which of the 32 rows
    const int t    = threadIdx.x;
    const int row  = bmf * KSEL + sub;

    // hist is dead before keys are written -> overlay (16 KB total)
    __shared__ union {
        int                s_hist[NBKT];    // 16 KB
        unsigned long long s_keys[CAP];     // 16 KB
    } ov;
    __shared__ int s_top[KSEL];
    __shared__ int s_cnt;
    __shared__ int s_bkt;
    __shared__ int s_target;

    if (b < NPAIR) {
        // =================== SELECT for bm = b (round-7 algorithm) =========
        const int bm   = b;
        const int m    = bm & (MROW - 1);
        const int lane = t & 31;
        const int warp = t >> 5;

        const int base = t * VPT;
        const float4* __restrict__ l4 = (const float4*)(logits + (size_t)m * NCOL);
        float f[VPT];
#pragma unroll
        for (int q = 0; q < 4; q++) {
            float4 ll = l4[(base >> 2) + q];
            f[q*4+0] = ll.x; f[q*4+1] = ll.y; f[q*4+2] = ll.z; f[q*4+3] = ll.w;
        }

#pragma unroll
        for (int i = 0; i < NBKT / (TPB * 4); i++)
            ((int4*)ov.s_hist)[t + i * TPB] = make_int4(0, 0, 0, 0);
        if (t == 0) s_cnt = 0;

        // per-thread top-4 prefilter (mapped-uint domain)
        unsigned um[VPT];
#pragma unroll
        for (int j = 0; j < VPT; j++) um[j] = fmap(f[j]);

        int      tj[4];
        unsigned tmu[4];
#pragma unroll
        for (int p = 0; p < 4; p++) {
            unsigned bv = um[0];
            int bj = 0;
#pragma unroll
            for (int j = 1; j < VPT; j++) if (um[j] > bv) { bv = um[j]; bj = j; }
            tj[p] = bj; tmu[p] = bv;
#pragma unroll
            for (int j = 0; j < VPT; j++) if (j == bj) um[j] = 0u;
        }

        // prefetch u for the 4 local-top candidates
        const float* __restrict__ urow = u + (size_t)bm * NCOL;
        float uu[4];
#pragma unroll
        for (int p = 0; p < 4; p++) uu[p] = urow[base + tj[p]];

        __syncthreads();   // hist zeroed

        // filtered histogram: 4 atomics/thread (under-count is conservative)
#pragma unroll
        for (int p = 0; p < 4; p++)
            atomicAdd(&ov.s_hist[tmu[p] >> 20], 1);
        __syncthreads();

        // warp 0: chunk scan for bucket where filtered-cum reaches 32
        if (warp == 0) {
            const unsigned FULL = 0xffffffffu;
            int cum = 0;
            for (int bb = NBKT - 64; bb >= 0; bb -= 64) {
                const int2 c = ((const int2*)(ov.s_hist + bb))[lane];
                const int pair  = c.x + c.y;
                const int total = __reduce_add_sync(FULL, pair);
                if (cum + total >= KSEL) {
                    int suf = pair;   // inclusive suffix sum over lanes
#pragma unroll
                    for (int off = 1; off < 32; off <<= 1) {
                        const int o = __shfl_down_sync(FULL, suf, off);
                        if (lane + off < 32) suf += o;
                    }
                    const int cx = cum + suf;
                    const unsigned bal = __ballot_sync(FULL, cx >= KSEL);
                    const int hi = 31 - __clz(bal);
                    if (lane == hi) {
                        const int cy = cx - c.x;
                        s_bkt = bb + lane * 2 + ((cy >= KSEL) ? 1 : 0);
                    }
                    break;
                }
                cum += total;
            }
        }

        // compute keys for prefetched candidates (overlaps scan)
        unsigned long long pkey[4];
#pragma unroll
        for (int p = 0; p < 4; p++) {
            const float gn  = -0.001f * __logf(-__logf(uu[p] + 1e-20f) + 1e-20f);
            const float val = unfmap(tmu[p]) + gn;
            pkey[p] = ((unsigned long long)fmap(val) << 32)
                    | (unsigned)(~(base + tj[p]));
        }
        __syncthreads();   // s_bkt ready; hist dead (union -> keys)

        // candidate gather: logit >= bucket_edge - MARGIN
        const float thrf = unfmap((unsigned)s_bkt << 20) - MARGIN;
        int nq = 0;
#pragma unroll
        for (int j = 0; j < VPT; j++) nq += (f[j] >= thrf) ? 1 : 0;

        if (nq <= 4) {
#pragma unroll
            for (int p = 0; p < 4; p++) {
                if (unfmap(tmu[p]) >= thrf) {
                    const int pos = atomicAdd(&s_cnt, 1);
                    if (pos < CAP) ov.s_keys[pos] = pkey[p];
                }
            }
        } else {
            // rare: thread holds >4 qualifying values — exact slow path
#pragma unroll
            for (int j = 0; j < VPT; j++) {
                if (f[j] >= thrf) {
                    const int pos = atomicAdd(&s_cnt, 1);
                    if (pos < CAP) {
                        const int idx = base + j;
                        const float u2 = urow[idx];
                        const float gn = -0.001f * __logf(-__logf(u2 + 1e-20f) + 1e-20f);
                        const float val = f[j] + gn;
                        ov.s_keys[pos] = ((unsigned long long)fmap(val) << 32)
                                       | (unsigned)(~idx);
                    }
                }
            }
        }
        __syncthreads();

        // parallel rank-count top-32 (all 256 threads)
        const int cnt = min(s_cnt, CAP);     // >= KSEL by construction
        for (int i = t; i < cnt; i += TPB) {
            const unsigned long long k = ov.s_keys[i];
            int r = 0;
            for (int j = 0; j < cnt; j++)
                r += (ov.s_keys[j] > k) ? 1 : 0;   // unique keys -> unique ranks
            if (r < KSEL) s_top[r] = (int)(~(unsigned)k);
        }
        __syncthreads();

        // index-rank sort -> ascending; publish (writers fence) + release flag
        if (t < KSEL) {
            const int myidx = s_top[t];
            int rank = 0;
#pragma unroll
            for (int j = 0; j < KSEL; j++) rank += (s_top[j] < myidx) ? 1 : 0;
            g_idx[bm * KSEL + rank] = myidx;
            __threadfence();                 // 512 blocks x 32 threads: cheap
        }
        __syncthreads();
        if (t == 0) atomicExch(&g_flag[bm], 1);   // release
    }

    // =================== ZERO FILL (no dependency — starts ASAP) ==========
    float4* __restrict__ o = reinterpret_cast<float4*>(out + (size_t)row * NCOL);
    const float4 z = make_float4(0.f, 0.f, 0.f, 0.f);
#pragma unroll
    for (int i = 0; i < 4; i++)
        o[t + i * TPB] = z;

    // =================== ACQUIRE + single 1.0 store ========================
    if (t == 0) {
        if (b >= NPAIR) {
            unsigned v;
            do {
                asm volatile("ld.global.acquire.gpu.b32 %0, [%1];"
                             : "=r"(v) : "l"(&g_flag[bmf]) : "memory");
                if (!v) __nanosleep(32);
            } while (!v);
        }
        s_target = g_idx[row];     // own block: visible via its own sync chain
    }
    __syncthreads();               // orders zero stores before the 1.0 store
    if (t == 0)
        out[(size_t)row * NCOL + s_target] = 1.0f;
}

extern "C" void kernel_launch(void* const* d_in, const int* in_sizes, int n_in,
                              void* d_out, int out_size)
{
    const float* logits = (const float*)d_in[0];   // (64, 4096) fp32
    const float* u      = (const float*)d_in[1];   // (8, 64, 4096) fp32
    float*       out    = (float*)d_out;           // (8, 64, 32, 4096) fp32

    reset_kernel<<<1, NPAIR>>>();
    fused_kernel<<<NROWS, TPB>>>(logits, u, out);
}

// round 11
// speedup vs baseline: 1.1671x; 1.0183x over previous
#include <cuda_runtime.h>
#include <cuda_bf16.h>
#include <math.h>

// Problem constants
#define BSZ   8
#define MROW  64
#define NCOL  4096
#define KSEL  32
#define NPAIR (BSZ * MROW)        // 512 (b,m) pairs
#define NROWS (NPAIR * KSEL)      // 16384 output rows / blocks
#define TPB   256                 // 8 warps
#define VPT   16                  // logits per thread (4096/256)
#define NBKT  4096                // histogram buckets (top 12 bits of fmap)
#define CAP   2048                // candidate cap (expected ~50-100)

// Noise bounds: gn = -0.001*log(-log(u+1e-20)+1e-20) in [-0.003830, +0.046052],
// span < 0.04989 -> margin 0.06 is strictly safe.
#define MARGIN 0.06f

// Static scratch (no allocation allowed)
__device__ int g_idx[NROWS];
__device__ int g_flag[NPAIR];

// Order-preserving float->uint map: a > b  <=>  fmap(a) > fmap(b). Bijective.
__device__ __forceinline__ unsigned fmap(float f) {
    unsigned b = __float_as_uint(f);
    return b ^ ((unsigned)(((int)b) >> 31) | 0x80000000u);
}
__device__ __forceinline__ float unfmap(unsigned m) {
    unsigned b = (m & 0x80000000u) ? (m ^ 0x80000000u) : ~m;
    return __uint_as_float(b);
}

// ---------------------------------------------------------------------------
// Reset flags each replay (graph-replay safety).
// ---------------------------------------------------------------------------
__global__ void reset_kernel()
{
    g_flag[threadIdx.x] = 0;
}

// ---------------------------------------------------------------------------
// Fused kernel: 16384 blocks; block b owns row (b&511)*32 + (b>>9).
// b<512: run exact top-32 select for bm=b, publish g_idx + release flag.
// ALL blocks: write their row of zeros IMMEDIATELY (no dependency), then
// acquire the flag (already set by then) and store the single 1.0.
// __launch_bounds__(TPB, 8): cap regs at 32 so the 15.9K fill-only blocks run
// at full occupancy; the 512 select blocks may spill (off critical path).
// ---------------------------------------------------------------------------
__global__ __launch_bounds__(TPB, 8)
void fused_kernel(const float* __restrict__ logits,
                  const float* __restrict__ u,
                  float* __restrict__ out)
{
    const int b    = blockIdx.x;            // 0..16383
    const int bmf  = b & (NPAIR - 1);       // bm whose row this block fills
    const int sub  = b >> 9;                // which of the 32 rows
    const int t    = threadIdx.x;
    const int row  = bmf * KSEL + sub;

    // hist is dead before keys are written -> overlay (16 KB total)
    __shared__ union {
        int                s_hist[NBKT];    // 16 KB
        unsigned long long s_keys[CAP];     // 16 KB
    } ov;
    __shared__ int s_top[KSEL];
    __shared__ int s_cnt;
    __shared__ int s_bkt;
    __shared__ int s_target;

    if (b < NPAIR) {
        // =================== SELECT for bm = b (round-7 algorithm) =========
        const int bm   = b;
        const int m    = bm & (MROW - 1);
        const int lane = t & 31;
        const int warp = t >> 5;

        const int base = t * VPT;
        const float4* __restrict__ l4 = (const float4*)(logits + (size_t)m * NCOL);
        float f[VPT];
#pragma unroll
        for (int q = 0; q < 4; q++) {
            float4 ll = l4[(base >> 2) + q];
            f[q*4+0] = ll.x; f[q*4+1] = ll.y; f[q*4+2] = ll.z; f[q*4+3] = ll.w;
        }

#pragma unroll
        for (int i = 0; i < NBKT / (TPB * 4); i++)
            ((int4*)ov.s_hist)[t + i * TPB] = make_int4(0, 0, 0, 0);
        if (t == 0) s_cnt = 0;

        // per-thread top-4 prefilter (mapped-uint domain)
        unsigned um[VPT];
#pragma unroll
        for (int j = 0; j < VPT; j++) um[j] = fmap(f[j]);

        int      tj[4];
        unsigned tmu[4];
#pragma unroll
        for (int p = 0; p < 4; p++) {
            unsigned bv = um[0];
            int bj = 0;
#pragma unroll
            for (int j = 1; j < VPT; j++) if (um[j] > bv) { bv = um[j]; bj = j; }
            tj[p] = bj; tmu[p] = bv;
#pragma unroll
            for (int j = 0; j < VPT; j++) if (j == bj) um[j] = 0u;
        }

        // prefetch u for the 4 local-top candidates
        const float* __restrict__ urow = u + (size_t)bm * NCOL;
        float uu[4];
#pragma unroll
        for (int p = 0; p < 4; p++) uu[p] = urow[base + tj[p]];

        __syncthreads();   // hist zeroed

        // filtered histogram: 4 atomics/thread (under-count is conservative)
#pragma unroll
        for (int p = 0; p < 4; p++)
            atomicAdd(&ov.s_hist[tmu[p] >> 20], 1);
        __syncthreads();

        // warp 0: chunk scan for bucket where filtered-cum reaches 32
        if (warp == 0) {
            const unsigned FULL = 0xffffffffu;
            int cum = 0;
            for (int bb = NBKT - 64; bb >= 0; bb -= 64) {
                const int2 c = ((const int2*)(ov.s_hist + bb))[lane];
                const int pair  = c.x + c.y;
                const int total = __reduce_add_sync(FULL, pair);
                if (cum + total >= KSEL) {
                    int suf = pair;   // inclusive suffix sum over lanes
#pragma unroll
                    for (int off = 1; off < 32; off <<= 1) {
                        const int o = __shfl_down_sync(FULL, suf, off);
                        if (lane + off < 32) suf += o;
                    }
                    const int cx = cum + suf;
                    const unsigned bal = __ballot_sync(FULL, cx >= KSEL);
                    const int hi = 31 - __clz(bal);
                    if (lane == hi) {
                        const int cy = cx - c.x;
                        s_bkt = bb + lane * 2 + ((cy >= KSEL) ? 1 : 0);
                    }
                    break;
                }
                cum += total;
            }
        }

        // compute keys for prefetched candidates (overlaps scan)
        unsigned long long pkey[4];
#pragma unroll
        for (int p = 0; p < 4; p++) {
            const float gn  = -0.001f * __logf(-__logf(uu[p] + 1e-20f) + 1e-20f);
            const float val = unfmap(tmu[p]) + gn;
            pkey[p] = ((unsigned long long)fmap(val) << 32)
                    | (unsigned)(~(base + tj[p]));
        }
        __syncthreads();   // s_bkt ready; hist dead (union -> keys)

        // candidate gather: logit >= bucket_edge - MARGIN
        const float thrf = unfmap((unsigned)s_bkt << 20) - MARGIN;
        int nq = 0;
#pragma unroll
        for (int j = 0; j < VPT; j++) nq += (f[j] >= thrf) ? 1 : 0;

        if (nq <= 4) {
#pragma unroll
            for (int p = 0; p < 4; p++) {
                if (unfmap(tmu[p]) >= thrf) {
                    const int pos = atomicAdd(&s_cnt, 1);
                    if (pos < CAP) ov.s_keys[pos] = pkey[p];
                }
            }
        } else {
            // rare: thread holds >4 qualifying values — exact slow path
#pragma unroll
            for (int j = 0; j < VPT; j++) {
                if (f[j] >= thrf) {
                    const int pos = atomicAdd(&s_cnt, 1);
                    if (pos < CAP) {
                        const int idx = base + j;
                        const float u2 = urow[idx];
                        const float gn = -0.001f * __logf(-__logf(u2 + 1e-20f) + 1e-20f);
                        const float val = f[j] + gn;
                        ov.s_keys[pos] = ((unsigned long long)fmap(val) << 32)
                                       | (unsigned)(~idx);
                    }
                }
            }
        }
        __syncthreads();

        // parallel rank-count top-32 (all 256 threads)
        const int cnt = min(s_cnt, CAP);     // >= KSEL by construction
        for (int i = t; i < cnt; i += TPB) {
            const unsigned long long k = ov.s_keys[i];
            int r = 0;
            for (int j = 0; j < cnt; j++)
                r += (ov.s_keys[j] > k) ? 1 : 0;   // unique keys -> unique ranks
            if (r < KSEL) s_top[r] = (int)(~(unsigned)k);
        }
        __syncthreads();

        // index-rank sort -> ascending; publish (writers fence) + release flag
        if (t < KSEL) {
            const int myidx = s_top[t];
            int rank = 0;
#pragma unroll
            for (int j = 0; j < KSEL; j++) rank += (s_top[j] < myidx) ? 1 : 0;
            g_idx[bm * KSEL + rank] = myidx;
            __threadfence();                 // 512 blocks x 32 threads: cheap
        }
        __syncthreads();
        if (t == 0) atomicExch(&g_flag[bm], 1);   // release
    }

    // =================== ZERO FILL (no dependency — starts ASAP) ==========
    float4* __restrict__ o = reinterpret_cast<float4*>(out + (size_t)row * NCOL);
    const float4 z = make_float4(0.f, 0.f, 0.f, 0.f);
#pragma unroll
    for (int i = 0; i < 4; i++)
        o[t + i * TPB] = z;

    // =================== ACQUIRE + single 1.0 store ========================
    if (t == 0) {
        if (b >= NPAIR) {
            unsigned v;
            do {
                asm volatile("ld.global.acquire.gpu.b32 %0, [%1];"
                             : "=r"(v) : "l"(&g_flag[bmf]) : "memory");
                if (!v) __nanosleep(32);
            } while (!v);
        }
        s_target = g_idx[row];     // own block: visible via its own sync chain
    }
    __syncthreads();               // orders zero stores before the 1.0 store
    if (t == 0)
        out[(size_t)row * NCOL + s_target] = 1.0f;
}

extern "C" void kernel_launch(void* const* d_in, const int* in_sizes, int n_in,
                              void* d_out, int out_size)
{
    const float* logits = (const float*)d_in[0];   // (64, 4096) fp32
    const float* u      = (const float*)d_in[1];   // (8, 64, 4096) fp32
    float*       out    = (float*)d_out;           // (8, 64, 32, 4096) fp32

    reset_kernel<<<1, NPAIR>>>();
    fused_kernel<<<NROWS, TPB>>>(logits, u, out);
}

// round 12
// speedup vs baseline: 1.1873x; 1.0173x over previous
#include <cuda_runtime.h>
#include <cuda_bf16.h>
#include <math.h>

// Problem constants
#define BSZ   8
#define MROW  64
#define NCOL  4096
#define KSEL  32
#define NPAIR (BSZ * MROW)        // 512 (b,m) pairs
#define NROWS (NPAIR * KSEL)      // 16384 output rows / blocks
#define TPB   256                 // 8 warps
#define VPT   16                  // logits per thread (4096/256)
#define NBKT  4096                // histogram buckets (top 12 bits of fmap)
#define CAP   2048                // candidate cap (expected ~100)

// Noise bounds: gn = -0.001*log(-log(u+1e-20)+1e-20) in [-0.003830, +0.046052],
// span < 0.04989 -> margin 0.06 is strictly safe.
#define MARGIN 0.06f

// Static scratch (no allocation allowed). Self-cleaning across launches:
// g_flag/g_done return to 0 at the end of every launch (see consumer code).
__device__ int g_idx[NROWS];
__device__ int g_flag[NPAIR];
__device__ int g_done[NPAIR];

// Order-preserving float->uint map: a > b  <=>  fmap(a) > fmap(b). Bijective.
__device__ __forceinline__ unsigned fmap(float f) {
    unsigned b = __float_as_uint(f);
    return b ^ ((unsigned)(((int)b) >> 31) | 0x80000000u);
}
__device__ __forceinline__ float unfmap(unsigned m) {
    unsigned b = (m & 0x80000000u) ? (m ^ 0x80000000u) : ~m;
    return __uint_as_float(b);
}

// ---------------------------------------------------------------------------
// Single fused kernel: 16384 blocks; block b owns row (b&511)*32 + (b>>9).
// b<512: run exact top-32 select for bm=b, publish g_idx + release flag.
// ALL blocks: write their row of zeros IMMEDIATELY (no dependency), then
// acquire the flag (set by then) and store the single 1.0.
// Exactly 31 consumer blocks per bm; the 31st resets flag+counter to zero so
// the next graph replay starts clean without a reset kernel.
// ---------------------------------------------------------------------------
__global__ __launch_bounds__(TPB, 8)
void fused_kernel(const float* __restrict__ logits,
                  const float* __restrict__ u,
                  float* __restrict__ out)
{
    const int b    = blockIdx.x;            // 0..16383
    const int bmf  = b & (NPAIR - 1);       // bm whose row this block fills
    const int sub  = b >> 9;                // which of the 32 rows
    const int t    = threadIdx.x;
    const int row  = bmf * KSEL + sub;

    // hist is dead before keys are written -> overlay (16 KB total)
    __shared__ union {
        int                s_hist[NBKT];    // 16 KB
        unsigned long long s_keys[CAP];     // 16 KB
    } ov;
    __shared__ int s_top[KSEL];
    __shared__ int s_cnt;
    __shared__ int s_bkt;
    __shared__ int s_target;

    if (b < NPAIR) {
        // =================== SELECT for bm = b =============================
        const int bm   = b;
        const int m    = bm & (MROW - 1);
        const int lane = t & 31;
        const int warp = t >> 5;

        // ---- Load logits row straight into mapped-uint domain ----
        const int base = t * VPT;
        const float4* __restrict__ l4 = (const float4*)(logits + (size_t)m * NCOL);
        unsigned um[VPT];
#pragma unroll
        for (int q = 0; q < 4; q++) {
            float4 ll = l4[(base >> 2) + q];
            um[q*4+0] = fmap(ll.x); um[q*4+1] = fmap(ll.y);
            um[q*4+2] = fmap(ll.z); um[q*4+3] = fmap(ll.w);
        }

        // ---- Zero histogram ----
#pragma unroll
        for (int i = 0; i < NBKT / (TPB * 4); i++)
            ((int4*)ov.s_hist)[t + i * TPB] = make_int4(0, 0, 0, 0);
        if (t == 0) s_cnt = 0;

        // ---- Prefilter: thread max only (1 atomic/thread; 256 counted
        //      real values >= 32 -> threshold conservative -> still exact) ----
        unsigned mx = um[0];
#pragma unroll
        for (int j = 1; j < VPT; j++) mx = max(mx, um[j]);
        __syncthreads();                     // hist zeroed
        atomicAdd(&ov.s_hist[mx >> 20], 1);
        __syncthreads();

        // ---- Warp 0: chunk scan for bucket where counted-cum reaches 32 ----
        if (warp == 0) {
            const unsigned FULL = 0xffffffffu;
            int cum = 0;
            for (int bb = NBKT - 64; bb >= 0; bb -= 64) {
                const int2 c = ((const int2*)(ov.s_hist + bb))[lane];
                const int pair  = c.x + c.y;
                const int total = __reduce_add_sync(FULL, pair);
                if (cum + total >= KSEL) {
                    int suf = pair;          // inclusive suffix sum over lanes
#pragma unroll
                    for (int off = 1; off < 32; off <<= 1) {
                        const int o = __shfl_down_sync(FULL, suf, off);
                        if (lane + off < 32) suf += o;
                    }
                    const int cx = cum + suf;
                    const unsigned bal = __ballot_sync(FULL, cx >= KSEL);
                    const int hi = 31 - __clz(bal);
                    if (lane == hi) {
                        const int cy = cx - c.x;
                        s_bkt = bb + lane * 2 + ((cy >= KSEL) ? 1 : 0);
                    }
                    break;
                }
                cum += total;
            }
        }
        __syncthreads();   // s_bkt ready; hist dead (union -> keys)

        // ---- Gather: mapped compare; u-load + Gumbel key only for ~100 ----
        const unsigned thrm = fmap(unfmap((unsigned)s_bkt << 20) - MARGIN);
        const float* __restrict__ urow = u + (size_t)bm * NCOL;
#pragma unroll
        for (int j = 0; j < VPT; j++) {
            if (um[j] >= thrm) {
                const int pos = atomicAdd(&s_cnt, 1);
                if (pos < CAP) {
                    const int idx = base + j;
                    const float u2 = urow[idx];
                    const float gn = -0.001f * __logf(-__logf(u2 + 1e-20f) + 1e-20f);
                    const float val = unfmap(um[j]) + gn;
                    // unique key; larger value wins, ties -> lower index
                    ov.s_keys[pos] = ((unsigned long long)fmap(val) << 32)
                                   | (unsigned)(~idx);
                }
            }
        }
        __syncthreads();

        // ---- Parallel rank-count top-32 (all 256 threads) ----
        const int cnt = min(s_cnt, CAP);     // >= KSEL by construction
        for (int i = t; i < cnt; i += TPB) {
            const unsigned long long k = ov.s_keys[i];
            int r = 0;
            for (int j = 0; j < cnt; j++)
                r += (ov.s_keys[j] > k) ? 1 : 0;   // unique keys -> unique ranks
            if (r < KSEL) s_top[r] = (int)(~(unsigned)k);
        }
        __syncthreads();

        // ---- Index-rank sort -> ascending; publish + release flag ----
        if (t < KSEL) {
            const int myidx = s_top[t];
            int rank = 0;
#pragma unroll
            for (int j = 0; j < KSEL; j++) rank += (s_top[j] < myidx) ? 1 : 0;
            g_idx[bm * KSEL + rank] = myidx;
            __threadfence();                 // release (512 blocks only: cheap)
        }
        __syncthreads();
        if (t == 0) atomicExch(&g_flag[bm], 1);
    }

    // =================== ZERO FILL (no dependency — starts ASAP) ==========
    float4* __restrict__ o = reinterpret_cast<float4*>(out + (size_t)row * NCOL);
    const float4 z = make_float4(0.f, 0.f, 0.f, 0.f);
#pragma unroll
    for (int i = 0; i < 4; i++)
        o[t + i * TPB] = z;

    // =================== ACQUIRE + single 1.0 store ========================
    if (t == 0) {
        if (b >= NPAIR) {
            unsigned v;
            do {
                asm volatile("ld.global.acquire.gpu.b32 %0, [%1];"
                             : "=r"(v) : "l"(&g_flag[bmf]) : "memory");
                if (!v) __nanosleep(32);
            } while (!v);
            s_target = g_idx[row];
            // exactly 31 consumers per bm; the last one resets the
            // synchronization state so the next replay starts clean
            const int old = atomicAdd(&g_done[bmf], 1);
            if (old == KSEL - 2) {           // 31st consumer
                atomicExch(&g_flag[bmf], 0);
                atomicExch(&g_done[bmf], 0);
            }
        } else {
            s_target = g_idx[row];           // own block: visible via sync chain
        }
    }
    __syncthreads();               // orders zero stores before the 1.0 store
    if (t == 0)
        out[(size_t)row * NCOL + s_target] = 1.0f;
}

extern "C" void kernel_launch(void* const* d_in, const int* in_sizes, int n_in,
                              void* d_out, int out_size)
{
    const float* logits = (const float*)d_in[0];   // (64, 4096) fp32
    const float* u      = (const float*)d_in[1];   // (8, 64, 4096) fp32
    float*       out    = (float*)d_out;           // (8, 64, 32, 4096) fp32

    fused_kernel<<<NROWS, TPB>>>(logits, u, out);
}

// round 14
// speedup vs baseline: 1.1927x; 1.0045x over previous
#include <cuda_runtime.h>
#include <cuda_bf16.h>
#include <math.h>

// Problem constants
#define BSZ   8
#define MROW  64
#define NCOL  4096
#define KSEL  32
#define NPAIR (BSZ * MROW)        // 512 (b,m) pairs
#define NROWS (NPAIR * KSEL)      // 16384 output rows
#define TPB   256                 // 8 warps
#define VPT   16                  // logits per thread (4096/256)
#define NBKT  4096                // histogram buckets (top 12 bits of fmap)
#define CAP   2048                // candidate cap (expected ~100)

// Noise bounds: gn = -0.001*log(-log(u+1e-20)+1e-20) in [-0.003830, +0.046052],
// span < 0.04989 -> margin 0.06 is strictly safe.
#define MARGIN 0.06f

// Static scratch (no allocation allowed). Self-cleaning across launches:
// g_flag/g_done return to 0 at the end of every launch (see consumer code).
__device__ int g_idx[NROWS];
__device__ int g_flag[NPAIR];
__device__ int g_done[NPAIR];

// Order-preserving float->uint map: a > b  <=>  fmap(a) > fmap(b). Bijective.
__device__ __forceinline__ unsigned fmap(float f) {
    unsigned b = __float_as_uint(f);
    return b ^ ((unsigned)(((int)b) >> 31) | 0x80000000u);
}
__device__ __forceinline__ float unfmap(unsigned m) {
    unsigned b = (m & 0x80000000u) ? (m ^ 0x80000000u) : ~m;
    return __uint_as_float(b);
}

// ---------------------------------------------------------------------------
// Split-grid fused kernel: grid = NPAIR + NROWS.
//   blocks [0, 512):        SELECT-ONLY for bm = b; release flag; retire fast.
//   blocks [512, 512+16384): FILL-ONLY for one row: zeros immediately
//                            (no dependency), then acquire flag + store 1.0.
// Select blocks have the lowest bids -> guaranteed wave 1 -> no deadlock.
// The 32nd consumer of each bm resets flag+counter (graph-replay safe).
// ---------------------------------------------------------------------------
__global__ __launch_bounds__(TPB, 8)
void fused_kernel(const float* __restrict__ logits,
                  const float* __restrict__ u,
                  float* __restrict__ out)
{
    const int b = blockIdx.x;
    const int t = threadIdx.x;

    if (b < NPAIR) {
        // =================== SELECT-ONLY for bm = b ========================
        // hist dead before keys are written -> overlay (16 KB).
        // __align__(16): int4 vector stores into s_hist require 16B alignment
        // (union's natural alignment is only 8 -> R13 trap).
        __shared__ __align__(16) union {
            int                s_hist[NBKT];
            unsigned long long s_keys[CAP];
        } ov;
        __shared__ int s_top[KSEL];
        __shared__ int s_cnt;
        __shared__ int s_bkt;

        const int bm   = b;
        const int m    = bm & (MROW - 1);
        const int lane = t & 31;
        const int warp = t >> 5;

        // ---- Load logits row straight into mapped-uint domain ----
        const int base = t * VPT;
        const float4* __restrict__ l4 = (const float4*)(logits + (size_t)m * NCOL);
        unsigned um[VPT];
#pragma unroll
        for (int q = 0; q < 4; q++) {
            float4 ll = l4[(base >> 2) + q];
            um[q*4+0] = fmap(ll.x); um[q*4+1] = fmap(ll.y);
            um[q*4+2] = fmap(ll.z); um[q*4+3] = fmap(ll.w);
        }

        // ---- Zero histogram ----
#pragma unroll
        for (int i = 0; i < NBKT / (TPB * 4); i++)
            ((int4*)ov.s_hist)[t + i * TPB] = make_int4(0, 0, 0, 0);
        if (t == 0) s_cnt = 0;

        // ---- Prefilter: thread max only (1 atomic/thread; 256 counted real
        //      values >= 32 -> threshold conservative -> still exact) ----
        unsigned mx = um[0];
#pragma unroll
        for (int j = 1; j < VPT; j++) mx = max(mx, um[j]);
        __syncthreads();                     // hist zeroed
        atomicAdd(&ov.s_hist[mx >> 20], 1);
        __syncthreads();

        // ---- Warp 0: chunk scan for bucket where counted-cum reaches 32 ----
        if (warp == 0) {
            const unsigned FULL = 0xffffffffu;
            int cum = 0;
            for (int bb = NBKT - 64; bb >= 0; bb -= 64) {
                const int2 c = ((const int2*)(ov.s_hist + bb))[lane];
                const int pair  = c.x + c.y;
                const int total = __reduce_add_sync(FULL, pair);
                if (cum + total >= KSEL) {
                    int suf = pair;          // inclusive suffix sum over lanes
#pragma unroll
                    for (int off = 1; off < 32; off <<= 1) {
                        const int o = __shfl_down_sync(FULL, suf, off);
                        if (lane + off < 32) suf += o;
                    }
                    const int cx = cum + suf;
                    const unsigned bal = __ballot_sync(FULL, cx >= KSEL);
                    const int hi = 31 - __clz(bal);
                    if (lane == hi) {
                        const int cy = cx - c.x;
                        s_bkt = bb + lane * 2 + ((cy >= KSEL) ? 1 : 0);
                    }
                    break;
                }
                cum += total;
            }
        }
        __syncthreads();   // s_bkt ready; hist dead (union -> keys)

        // ---- Gather: mapped compare; u-load + Gumbel key only for ~100 ----
        const unsigned thrm = fmap(unfmap((unsigned)s_bkt << 20) - MARGIN);
        const float* __restrict__ urow = u + (size_t)bm * NCOL;
#pragma unroll
        for (int j = 0; j < VPT; j++) {
            if (um[j] >= thrm) {
                const int pos = atomicAdd(&s_cnt, 1);
                if (pos < CAP) {
                    const int idx = base + j;
                    const float u2 = urow[idx];
                    const float gn = -0.001f * __logf(-__logf(u2 + 1e-20f) + 1e-20f);
                    const float val = unfmap(um[j]) + gn;
                    // unique key; larger value wins, ties -> lower index
                    ov.s_keys[pos] = ((unsigned long long)fmap(val) << 32)
                                   | (unsigned)(~idx);
                }
            }
        }
        __syncthreads();

        // ---- Parallel rank-count top-32 (all 256 threads) ----
        const int cnt = min(s_cnt, CAP);     // >= KSEL by construction
        for (int i = t; i < cnt; i += TPB) {
            const unsigned long long k = ov.s_keys[i];
            int r = 0;
            for (int j = 0; j < cnt; j++)
                r += (ov.s_keys[j] > k) ? 1 : 0;   // unique keys -> unique ranks
            if (r < KSEL) s_top[r] = (int)(~(unsigned)k);
        }
        __syncthreads();

        // ---- Index-rank sort -> ascending; publish + release flag ----
        if (t < KSEL) {
            const int myidx = s_top[t];
            int rank = 0;
#pragma unroll
            for (int j = 0; j < KSEL; j++) rank += (s_top[j] < myidx) ? 1 : 0;
            g_idx[bm * KSEL + rank] = myidx;
            __threadfence();                 // release (512 blocks only: cheap)
        }
        __syncthreads();
        if (t == 0) atomicExch(&g_flag[bm], 1);
        return;                              // retire fast, free the slot
    }

    // ====================== FILL-ONLY block ================================
    const int f    = b - NPAIR;              // 0..16383
    const int bmf  = f & (NPAIR - 1);
    const int sub  = f >> 9;
    const int row  = bmf * KSEL + sub;

    __shared__ int s_target;

    // ---- Zeros immediately (no dependency on select) ----
    float4* __restrict__ o = reinterpret_cast<float4*>(out + (size_t)row * NCOL);
    const float4 z = make_float4(0.f, 0.f, 0.f, 0.f);
#pragma unroll
    for (int i = 0; i < 4; i++)
        o[t + i * TPB] = z;

    // ---- Acquire flag (selects complete ~4us into the kernel) ----
    if (t == 0) {
        unsigned v;
        do {
            asm volatile("ld.global.acquire.gpu.b32 %0, [%1];"
                         : "=r"(v) : "l"(&g_flag[bmf]) : "memory");
            if (!v) __nanosleep(32);
        } while (!v);
        s_target = g_idx[row];
        // 32 consumers per bm; the last resets sync state (replay-safe)
        const int old = atomicAdd(&g_done[bmf], 1);
        if (old == KSEL - 1) {
            atomicExch(&g_flag[bmf], 0);
            atomicExch(&g_done[bmf], 0);
        }
    }
    __syncthreads();               // orders zero stores before the 1.0 store
    if (t == 0)
        out[(size_t)row * NCOL + s_target] = 1.0f;
}

extern "C" void kernel_launch(void* const* d_in, const int* in_sizes, int n_in,
                              void* d_out, int out_size)
{
    const float* logits = (const float*)d_in[0];   // (64, 4096) fp32
    const float* u      = (const float*)d_in[1];   // (8, 64, 4096) fp32
    float*       out    = (float*)d_out;           // (8, 64, 32, 4096) fp32

    fused_kernel<<<NPAIR + NROWS, TPB>>>(logits, u, out);
}